// round 11
// baseline (speedup 1.0000x reference)
#include <cuda_runtime.h>
#include <cstdint>

#define NPTS   300000
#define KOFF   27
#define NPAIR  100000
#define CIN    32
#define COUT   64
#define TOT_PAIRS (KOFF * NPAIR)
#define EPS    1e-5
#define NEG_SLOPE 0.01f
#define NBUCK  8
#define BUCK_DIV 37500          // in/37500 <= 7 for in < 300000
#define NSEG   (KOFF * NBUCK)   // 216
#define HIST_BLOCKS 660

// ---------------- device scratch (no allocations allowed) ----------------
// g_histPart is fully overwritten every replay (plain stores) -> no pre-zero.
__device__ int    g_histPart[HIST_BLOCKS][NSEG];   // per-block partial histograms
__device__ int    g_segStart[NSEG + 1];
__device__ int    g_cursor[NSEG];
__device__ int2   g_sorted[TOT_PAIRS];   // (in,out) pairs, bucket-sorted per k
__device__ double g_stats[16];           // zeroed by scan_kernel each replay

// ---------------- pure, deterministic idx-dtype detection ----------------
// Reference declares int64 indices but JAX w/o x64 silently emits int32.
// Reading int32 data as int64 fuses two indices (lo + hi*2^32); hi is a
// ~uniform idx so virtually every sample blows past NPTS unless truly int64.
__device__ __forceinline__ int detect64(const void* in_idx) {
    const long long* p = (const long long*)in_idx;
    int ok = 1;
#pragma unroll
    for (int s = 0; s < 16; s++) {
        long long slot = (long long)s * (TOT_PAIRS / 2 - 1) / 15;
        long long v = __ldg(p + slot);
        if (v < 0 || v >= NPTS) ok = 0;
    }
    return ok;
}

// ---------------- k1: per-block histogram over (k, bucket) ----------------
__global__ __launch_bounds__(256) void hist_kernel(const void* in_idx) {
    __shared__ int h[NSEG];
    __shared__ int s64;
    int t = threadIdx.x;
    for (int i = t; i < NSEG; i += blockDim.x) h[i] = 0;
    if (t == 0) s64 = detect64(in_idx);
    __syncthreads();
    int is64 = s64;
    int stride = gridDim.x * blockDim.x;
    for (int j = blockIdx.x * blockDim.x + t; j < TOT_PAIRS; j += stride) {
        int in = is64 ? (int)((const long long*)in_idx)[j]
                      : ((const int*)in_idx)[j];
        int k = j / NPAIR;
        int b = in / BUCK_DIV;
        atomicAdd(&h[k * NBUCK + b], 1);
    }
    __syncthreads();
    for (int i = t; i < NSEG; i += blockDim.x)
        g_histPart[blockIdx.x][i] = h[i];           // plain store, no pre-zero needed
}

// ---------------- k2: sum partials + exclusive scan + zero stats ----------
__global__ __launch_bounds__(256) void scan_kernel() {
    __shared__ int sm[256];
    int t = threadIdx.x;
    int tot = 0;
    if (t < NSEG) {
        for (int b = 0; b < HIST_BLOCKS; b++) tot += g_histPart[b][t];
    }
    sm[t] = tot;
    __syncthreads();
    for (int d = 1; d < 256; d <<= 1) {
        int v = (t >= d) ? sm[t - d] : 0;
        __syncthreads();
        sm[t] += v;
        __syncthreads();
    }
    int excl = (t == 0) ? 0 : sm[t - 1];
    if (t <= NSEG) g_segStart[t] = excl;
    if (t < NSEG)  g_cursor[t]   = excl;
    if (t < 16)    g_stats[t]    = 0.0;   // re-zeroed every replay, before reduce
}

// ---------------- k3: scatter pairs into bucket-sorted order ----------------
__global__ __launch_bounds__(256) void fill_kernel(const void* in_idx, const void* out_idx) {
    __shared__ int s64;
    if (threadIdx.x == 0) s64 = detect64(in_idx);
    __syncthreads();
    int is64 = s64;
    int stride = gridDim.x * blockDim.x;
    for (int j = blockIdx.x * blockDim.x + threadIdx.x; j < TOT_PAIRS; j += stride) {
        int in, out;
        if (is64) {
            in  = (int)((const long long*)in_idx)[j];
            out = (int)((const long long*)out_idx)[j];
        } else {
            in  = ((const int*)in_idx)[j];
            out = ((const int*)out_idx)[j];
        }
        int k = j / NPAIR;
        int b = in / BUCK_DIV;
        int pos = atomicAdd(&g_cursor[k * NBUCK + b], 1);
        g_sorted[pos] = make_int2(in, out);
    }
}

// ---------------- k4 (ncu capture slot): conv over bucket-ordered pairs ----
// R10 body (bucket-sorted gathers, weights in registers) with one change:
// the scatter. Lane pair (2m, 2m+1) owns channels 4m..4m+3; odd lane's two
// partials move to the even lane via shfl_down, and the even lane issues ONE
// red.global.add.v4.f32 under an inline-asm predicate (no BSSY/BSYNC branch
// -- the C++ `if` version of this regressed 550us in R6). 16 REDG lanes
// per pair instead of 32.
__global__ __launch_bounds__(128) void conv_kernel(
    const float* __restrict__ feats,
    const float* __restrict__ weight,
    float* __restrict__ out)
{
    int k    = blockIdx.y;
    int lane = threadIdx.x & 31;
    int warp = threadIdx.x >> 5;

    const float* W = weight + k * (CIN * COUT);
    float w0[CIN], w1[CIN];
#pragma unroll
    for (int i = 0; i < CIN; i++) {
        float2 wv = *(const float2*)(W + i * COUT + 2 * lane);
        w0[i] = wv.x; w1[i] = wv.y;
    }

    int wstride = gridDim.x * 4;
    int evenLane = lane & 1;            // 0 on even lanes (predicate source)

    for (int b = 0; b < NBUCK; b++) {
        int s0 = __ldg(&g_segStart[k * NBUCK + b]);
        int s1 = __ldg(&g_segStart[k * NBUCK + b + 1]);

        for (int p = s0 + blockIdx.x * 4 + warp; p < s1; p += wstride) {
            int2 io = __ldcs(&g_sorted[p]);

            const float4* xr = (const float4*)(feats + (size_t)io.x * CIN);
            float x[CIN];
#pragma unroll
            for (int j = 0; j < 8; j++) ((float4*)x)[j] = __ldg(xr + j);

            float y0 = 0.f, y1 = 0.f, y2 = 0.f, y3 = 0.f;
#pragma unroll
            for (int i = 0; i < CIN; i += 2) {
                y0 = fmaf(x[i],     w0[i],     y0);
                y1 = fmaf(x[i],     w1[i],     y1);
                y2 = fmaf(x[i + 1], w0[i + 1], y2);
                y3 = fmaf(x[i + 1], w1[i + 1], y3);
            }
            float r0 = y0 + y2;   // channel 2*lane
            float r1 = y1 + y3;   // channel 2*lane+1

            // move odd lane's partials to even lane; even lane covers 4m..4m+3
            float s2 = __shfl_down_sync(0xffffffffu, r0, 1);
            float s3 = __shfl_down_sync(0xffffffffu, r1, 1);

            float* dst = out + (size_t)io.y * COUT + 2 * lane;  // even: 16B aligned
            asm volatile(
                "{ .reg .pred p;\n\t"
                "  setp.eq.b32 p, %5, 0;\n\t"
                "  @p red.global.add.v4.f32 [%0], {%1, %2, %3, %4}; }"
                :: "l"(dst), "f"(r0), "f"(r1), "f"(s2), "f"(s3), "r"(evenLane)
                : "memory");
        }
    }
}

// ---------------- k5: group stats ----------------
// blockDim = 256 (multiple of 16) so (flat_float4_index & 15) == (tid & 15):
// each thread touches exactly ONE group -> scalar accumulators, no spills.
__global__ __launch_bounds__(256) void reduce_kernel(const float* __restrict__ out) {
    __shared__ double ssum[16];
    int t = threadIdx.x;
    if (t < 16) ssum[t] = 0.0;
    __syncthreads();

    long long total4 = (long long)NPTS * COUT / 4;
    long long stride = (long long)gridDim.x * 256;
    float s = 0.f, q = 0.f;
    for (long long j = (long long)blockIdx.x * 256 + t; j < total4; j += stride) {
        float4 v = __ldg(((const float4*)out) + j);
        s += (v.x + v.y) + (v.z + v.w);
        q += (v.x * v.x + v.y * v.y) + (v.z * v.z + v.w * v.w);
    }
    s += __shfl_xor_sync(0xffffffffu, s, 16);
    q += __shfl_xor_sync(0xffffffffu, q, 16);
    s += __shfl_xor_sync(0xffffffffu, s, 1);
    q += __shfl_xor_sync(0xffffffffu, q, 1);
    int lane = t & 31;
    if ((lane & 16) == 0 && (lane & 1) == 0) {
        int g = lane >> 1;
        atomicAdd(&ssum[g],     (double)s);
        atomicAdd(&ssum[8 + g], (double)q);
    }
    __syncthreads();
    if (t < 16) atomicAdd(&g_stats[t], ssum[t]);
}

// ---------------- k6: normalize + affine + LeakyReLU ----------------
__global__ __launch_bounds__(256) void norm_kernel(
    float* __restrict__ out,
    const float* __restrict__ gamma,
    const float* __restrict__ beta)
{
    int t  = threadIdx.x;
    int c4 = t & 15;          // float4 slot within the 64-channel row
    int g  = c4 >> 1;

    double cnt = (double)NPTS * 8.0;
    double m   = g_stats[g] / cnt;
    double var = g_stats[8 + g] / cnt - m * m;
    float mean = (float)m;
    float rstd = (float)(1.0 / sqrt(var + EPS));

    float4 ga = __ldg(((const float4*)gamma) + c4);
    float4 be = __ldg(((const float4*)beta) + c4);
    float4 sc, of;
    sc.x = rstd * ga.x; of.x = be.x - mean * sc.x;
    sc.y = rstd * ga.y; of.y = be.y - mean * sc.y;
    sc.z = rstd * ga.z; of.z = be.z - mean * sc.z;
    sc.w = rstd * ga.w; of.w = be.w - mean * sc.w;

    long long total4 = (long long)NPTS * COUT / 4;
    long long stride = (long long)gridDim.x * 256;
    for (long long j = (long long)blockIdx.x * 256 + t; j < total4; j += stride) {
        float4 v = ((float4*)out)[j];
        v.x = fmaf(v.x, sc.x, of.x);
        v.y = fmaf(v.y, sc.y, of.y);
        v.z = fmaf(v.z, sc.z, of.z);
        v.w = fmaf(v.w, sc.w, of.w);
        v.x = v.x >= 0.f ? v.x : NEG_SLOPE * v.x;
        v.y = v.y >= 0.f ? v.y : NEG_SLOPE * v.y;
        v.z = v.z >= 0.f ? v.z : NEG_SLOPE * v.z;
        v.w = v.w >= 0.f ? v.w : NEG_SLOPE * v.w;
        ((float4*)out)[j] = v;
    }
}

// ---------------- launcher ----------------
extern "C" void kernel_launch(void* const* d_in, const int* in_sizes, int n_in,
                              void* d_out, int out_size) {
    const float* feats  = (const float*)d_in[0];
    const float* weight = (const float*)d_in[1];
    const float* gamma  = (const float*)d_in[2];
    const float* beta   = (const float*)d_in[3];
    const void*  in_idx = d_in[4];
    const void*  out_idx= d_in[5];
    float* out = (float*)d_out;

    cudaMemsetAsync(d_out, 0, (size_t)out_size * sizeof(float), 0);

    hist_kernel<<<HIST_BLOCKS, 256>>>(in_idx);                 // kernel 1
    scan_kernel<<<1, 256>>>();                                 // kernel 2
    fill_kernel<<<660, 256>>>(in_idx, out_idx);                // kernel 3
    conv_kernel<<<dim3(27, KOFF), 128>>>(feats, weight, out);  // kernel 4 <- ncu
    reduce_kernel<<<296, 256>>>(out);                          // kernel 5
    norm_kernel<<<592, 256>>>(out, gamma, beta);               // kernel 6
}